// round 14
// baseline (speedup 1.0000x reference)
#include <cuda_runtime.h>

#define H 512
#define W 512
#define B 64
#define RB 16
#define NSTRIPS (H / RB)   // 32
#define NT 128
#define NBLK (B * NSTRIPS) // 2048

typedef unsigned long long u64;

// Per-block partials: [blk*3+0]=mass_raw, +1=mom_raw, +2=l1.
// Every block writes its slot on every launch -> no init kernel needed.
__device__ float g_part[NBLK * 3];

// ---------- packed f32x2 helpers ----------
__device__ __forceinline__ u64 padd(u64 a, u64 b) {
    u64 r; asm("add.rn.f32x2 %0, %1, %2;" : "=l"(r) : "l"(a), "l"(b)); return r;
}
__device__ __forceinline__ u64 pmul(u64 a, u64 b) {
    u64 r; asm("mul.rn.f32x2 %0, %1, %2;" : "=l"(r) : "l"(a), "l"(b)); return r;
}
__device__ __forceinline__ u64 pfma(u64 a, u64 b, u64 c) {
    u64 r; asm("fma.rn.f32x2 %0, %1, %2, %3;" : "=l"(r) : "l"(a), "l"(b), "l"(c)); return r;
}
__device__ __forceinline__ u64 pdup(float x) {
    unsigned u = __float_as_uint(x);
    return ((u64)u << 32) | (u64)u;
}
#define NEG1_C 0xBF800000BF800000ULL   // (-1.0f, -1.0f)
__device__ __forceinline__ u64 psub(u64 a, u64 b) {   // a - b
    return pfma(b, (u64)NEG1_C, a);
}
__device__ __forceinline__ u64 pabs(u64 a) { return a & 0x7FFFFFFF7FFFFFFFULL; }
__device__ __forceinline__ float plo(u64 a) { return __uint_as_float((unsigned)a); }
__device__ __forceinline__ float phi(u64 a) { return __uint_as_float((unsigned)(a >> 32)); }
__device__ __forceinline__ u64 ppack(float lo, float hi) {
    return ((u64)__float_as_uint(hi) << 32) | (u64)__float_as_uint(lo);
}

struct Row { u64 a, b; };   // a = cols (4t,4t+1), b = cols (4t+2,4t+3)

__device__ __forceinline__ Row ldrow(const float* __restrict__ rowbase, int t) {
    ulonglong2 q = *(reinterpret_cast<const ulonglong2*>(rowbase) + t);
    Row r; r.a = q.x; r.b = q.y; return r;
}

// shifted column pairs for one plane's cur row:
// A=(c[-1],c0)  Bp=(c1,c2)  Cp=(c3,c[+4])
__device__ __forceinline__ void shifts(Row c, const float* __restrict__ rowbase,
                                       int tid, int lane, u64& A, u64& Bp, u64& Cp) {
    float c0 = plo(c.a), c1 = phi(c.a), c2 = plo(c.b), c3 = phi(c.b);
    float vL = __shfl_up_sync(0xFFFFFFFFu, c3, 1);
    float vR = __shfl_down_sync(0xFFFFFFFFu, c0, 1);
    if (lane == 0 && tid > 0)       vL = rowbase[4 * tid - 1];
    if (lane == 31 && tid < NT - 1) vR = rowbase[4 * tid + 4];
    A  = ppack(vL, c0);
    Bp = ppack(c1, c2);
    Cp = ppack(c3, vR);
}

// Raw (unscaled) residuals for 2 columns.
// mass_raw = (ur-ul)+(vt-vb)                        -> *0.5  at finalize
// momu_raw = (du2+duv) - 4*IRE*(ur+ul+ut+ub-4um)    -> *0.25 at finalize
__device__ __forceinline__ void resid_slot(
    u64 um, u64 ul, u64 ur, u64 ub, u64 ut,
    u64 vm, u64 vl, u64 vr, u64 vb, u64 vt,
    u64 TWO, u64 NEG4, u64 N4IRE,
    u64& mass, u64& momu, u64& momv)
{
    u64 t1 = psub(ur, ul);
    u64 t3 = psub(vt, vb);
    mass = padd(t1, t3);

    u64 s1 = padd(ur, ul);
    u64 w1 = pfma(um, TWO, s1);
    u64 du2 = pmul(t1, w1);                 // (ur+um)^2-(ul+um)^2  (raw)
    u64 s3 = padd(vt, vb);
    u64 w3 = pfma(vm, TWO, s3);
    u64 dv2 = pmul(t3, w3);

    u64 p1 = padd(ut, um), p2 = padd(vt, vm);
    u64 p3 = padd(ub, um), p4 = padd(vb, vm);
    u64 duv = psub(pmul(p1, p2), pmul(p3, p4));

    u64 p6 = padd(ur, um), p8 = padd(ul, um);
    u64 p5 = padd(vr, vm), p7 = padd(vl, vm);
    u64 dvu = psub(pmul(p5, p6), pmul(p7, p8));

    u64 Xu = padd(du2, duv);
    u64 Xv = padd(dvu, dv2);

    u64 s5 = padd(ut, ub);
    u64 s6 = padd(s1, s5);
    u64 Yu = pfma(um, NEG4, s6);            // ur+ul+ut+ub-4um
    momu = pfma(Yu, N4IRE, Xu);

    u64 s8 = padd(vr, vl);
    u64 s9 = padd(s3, s8);
    u64 Yv = pfma(vm, NEG4, s9);
    momv = pfma(Yv, N4IRE, Xv);
}

__global__ __launch_bounds__(NT) void loss_kernel(const float* __restrict__ pred,
                                                  const float* __restrict__ trut)
{
    const int bx = blockIdx.x;
    const int img = bx >> 5;               // / NSTRIPS
    const int strip = bx & (NSTRIPS - 1);
    const int y0 = strip * RB;
    const int tid = threadIdx.x;
    const int lane = tid & 31;

    const size_t HW = (size_t)H * W;
    const float* __restrict__ pu = pred + (size_t)img * 2 * HW;
    const float* __restrict__ pv = pu + HW;
    const float* __restrict__ tu = trut + (size_t)img * 2 * HW;
    const float* __restrict__ tv = tu + HW;

    const u64 TWO   = pdup(2.0f);
    const u64 NEG4  = pdup(-4.0f);
    const u64 N4IRE = pdup(-(4.0f * (1.0f / 400.0f)));   // -0.01

    Row uPp = {0, 0}, vPp = {0, 0}, uTp = {0, 0}, vTp = {0, 0};
    if (y0 > 0) {
        uPp = ldrow(pu + (size_t)(y0 - 1) * W, tid);
        vPp = ldrow(pv + (size_t)(y0 - 1) * W, tid);
        uTp = ldrow(tu + (size_t)(y0 - 1) * W, tid);
        vTp = ldrow(tv + (size_t)(y0 - 1) * W, tid);
    }
    Row uPc = ldrow(pu + (size_t)y0 * W, tid);
    Row vPc = ldrow(pv + (size_t)y0 * W, tid);
    Row uTc = ldrow(tu + (size_t)y0 * W, tid);
    Row vTc = ldrow(tv + (size_t)y0 * W, tid);
    Row uPn = ldrow(pu + (size_t)(y0 + 1) * W, tid);
    Row vPn = ldrow(pv + (size_t)(y0 + 1) * W, tid);
    Row uTn = ldrow(tu + (size_t)(y0 + 1) * W, tid);
    Row vTn = ldrow(tv + (size_t)(y0 + 1) * W, tid);

    u64 accM0 = 0, accM1 = 0, accO0 = 0, accO1 = 0, accL0 = 0, accL1 = 0;

    #pragma unroll 4
    for (int r = 0; r < RB; ++r) {
        const int y = y0 + r;

        // prefetch row y+2 (consumed as 'next' at iteration r+1)
        Row nuP = {0, 0}, nvP = {0, 0}, nuT = {0, 0}, nvT = {0, 0};
        const int yn = y + 2;
        if (r < RB - 1 && yn < H) {
            nuP = ldrow(pu + (size_t)yn * W, tid);
            nvP = ldrow(pv + (size_t)yn * W, tid);
            nuT = ldrow(tu + (size_t)yn * W, tid);
            nvT = ldrow(tv + (size_t)yn * W, tid);
        }

        // L1 (all points)
        accL0 = padd(accL0, pabs(psub(uPc.a, uTc.a)));
        accL1 = padd(accL1, pabs(psub(uPc.b, uTc.b)));
        accL0 = padd(accL0, pabs(psub(vPc.a, vTc.a)));
        accL1 = padd(accL1, pabs(psub(vPc.b, vTc.b)));

        if (y >= 1 && y <= H - 2) {
            u64 uA, uB, uC, vA, vB, vC;
            // pred
            shifts(uPc, pu + (size_t)y * W, tid, lane, uA, uB, uC);
            shifts(vPc, pv + (size_t)y * W, tid, lane, vA, vB, vC);
            u64 mP0, oP0, wP0, mP1, oP1, wP1;
            resid_slot(uPc.a, uPp.a, uPn.a, uA, uB,
                       vPc.a, vPp.a, vPn.a, vA, vB,
                       TWO, NEG4, N4IRE, mP0, oP0, wP0);
            resid_slot(uPc.b, uPp.b, uPn.b, uB, uC,
                       vPc.b, vPp.b, vPn.b, vB, vC,
                       TWO, NEG4, N4IRE, mP1, oP1, wP1);
            // trut
            shifts(uTc, tu + (size_t)y * W, tid, lane, uA, uB, uC);
            shifts(vTc, tv + (size_t)y * W, tid, lane, vA, vB, vC);
            u64 mT0, oT0, wT0, mT1, oT1, wT1;
            resid_slot(uTc.a, uTp.a, uTn.a, uA, uB,
                       vTc.a, vTp.a, vTn.a, vA, vB,
                       TWO, NEG4, N4IRE, mT0, oT0, wT0);
            resid_slot(uTc.b, uTp.b, uTn.b, uB, uC,
                       vTc.b, vTp.b, vTn.b, vB, vC,
                       TWO, NEG4, N4IRE, mT1, oT1, wT1);

            accM0 = padd(accM0, pabs(psub(mT0, mP0)));
            accM1 = padd(accM1, pabs(psub(mT1, mP1)));
            accO0 = padd(accO0, padd(pabs(psub(oT0, oP0)), pabs(psub(wT0, wP0))));
            accO1 = padd(accO1, padd(pabs(psub(oT1, oP1)), pabs(psub(wT1, wP1))));
        }

        // rotate sliding window
        uPp = uPc; uPc = uPn; uPn = nuP;
        vPp = vPc; vPc = vPn; vPn = nvP;
        uTp = uTc; uTc = uTn; uTn = nuT;
        vTp = vTc; vTc = vTn; vTn = nvT;
    }

    // mask out boundary columns 0 and 511 (excluded from stencil sums)
    if (tid == 0)      { accM0 &= 0xFFFFFFFF00000000ULL; accO0 &= 0xFFFFFFFF00000000ULL; }
    if (tid == NT - 1) { accM1 &= 0x00000000FFFFFFFFULL; accO1 &= 0x00000000FFFFFFFFULL; }

    float sM = plo(accM0) + phi(accM0) + plo(accM1) + phi(accM1);
    float sO = plo(accO0) + phi(accO0) + plo(accO1) + phi(accO1);
    float sL = plo(accL0) + phi(accL0) + plo(accL1) + phi(accL1);

    // block reduce (4 warps)
    const unsigned FULL = 0xFFFFFFFFu;
    #pragma unroll
    for (int off = 16; off > 0; off >>= 1) {
        sM += __shfl_down_sync(FULL, sM, off);
        sO += __shfl_down_sync(FULL, sO, off);
        sL += __shfl_down_sync(FULL, sL, off);
    }
    __shared__ float sh[4][3];
    const int wid = tid >> 5;
    if (lane == 0) { sh[wid][0] = sM; sh[wid][1] = sO; sh[wid][2] = sL; }
    __syncthreads();
    if (tid == 0) {
        g_part[bx * 3 + 0] = sh[0][0] + sh[1][0] + sh[2][0] + sh[3][0];
        g_part[bx * 3 + 1] = sh[0][1] + sh[1][1] + sh[2][1] + sh[3][1];
        g_part[bx * 3 + 2] = sh[0][2] + sh[1][2] + sh[2][2] + sh[3][2];
    }
}

__global__ __launch_bounds__(256) void finalize_kernel(float* __restrict__ out) {
    const int tid = threadIdx.x;
    const int lane = tid & 31;
    const int wid = tid >> 5;

    double dm = 0.0, dO = 0.0, dl = 0.0;
    for (int i = tid; i < NBLK; i += 256) {
        dm += (double)g_part[i * 3 + 0];
        dO += (double)g_part[i * 3 + 1];
        dl += (double)g_part[i * 3 + 2];
    }
    const unsigned FULL = 0xFFFFFFFFu;
    #pragma unroll
    for (int off = 16; off > 0; off >>= 1) {
        dm += __shfl_down_sync(FULL, dm, off);
        dO += __shfl_down_sync(FULL, dO, off);
        dl += __shfl_down_sync(FULL, dl, off);
    }
    __shared__ double shd[8][3];
    if (lane == 0) { shd[wid][0] = dm; shd[wid][1] = dO; shd[wid][2] = dl; }
    __syncthreads();
    if (tid == 0) {
        double m = 0.0, o = 0.0, l = 0.0;
        #pragma unroll
        for (int i = 0; i < 8; ++i) { m += shd[i][0]; o += shd[i][1]; l += shd[i][2]; }
        const double NM = (double)B * (H - 2) * (W - 2);   // 64*510*510
        const double NL = (double)B * 2.0 * H * W;         // 64*2*512*512
        double lossMass = 0.5  * m / NM;
        double lossMom  = 0.25 * o / NM;
        double lossL1   = l / NL;
        out[0] = (float)((lossMass * 5.0 + lossMom * 25.0 + lossL1) / 3.0);
    }
}

extern "C" void kernel_launch(void* const* d_in, const int* in_sizes, int n_in,
                              void* d_out, int out_size) {
    const float* pred = (const float*)d_in[0];
    const float* trut = (const float*)d_in[1];
    float* out = (float*)d_out;

    loss_kernel<<<NBLK, NT>>>(pred, trut);
    finalize_kernel<<<1, 256>>>(out);
}

// round 15
// speedup vs baseline: 1.0882x; 1.0882x over previous
#include <cuda_runtime.h>

#define H 512
#define W 512
#define B 64
#define RB 16
#define NSTRIPS (H / RB)   // 32
#define NT 128

typedef unsigned long long u64;

// Accumulators. Zero at process start; finalize_kernel resets them to zero
// after consuming, so the invariant "g_sums==0 at loss_kernel entry" holds
// for every graph replay. Deterministic: same inputs -> same sums -> same out.
__device__ double g_sums[3];   // [0]=mass_raw, [1]=mom_raw, [2]=l1

// ---------- packed f32x2 helpers ----------
__device__ __forceinline__ u64 padd(u64 a, u64 b) {
    u64 r; asm("add.rn.f32x2 %0, %1, %2;" : "=l"(r) : "l"(a), "l"(b)); return r;
}
__device__ __forceinline__ u64 pmul(u64 a, u64 b) {
    u64 r; asm("mul.rn.f32x2 %0, %1, %2;" : "=l"(r) : "l"(a), "l"(b)); return r;
}
__device__ __forceinline__ u64 pfma(u64 a, u64 b, u64 c) {
    u64 r; asm("fma.rn.f32x2 %0, %1, %2, %3;" : "=l"(r) : "l"(a), "l"(b), "l"(c)); return r;
}
__device__ __forceinline__ u64 pdup(float x) {
    unsigned u = __float_as_uint(x);
    return ((u64)u << 32) | (u64)u;
}
#define NEG1_C 0xBF800000BF800000ULL   // (-1.0f, -1.0f)
__device__ __forceinline__ u64 psub(u64 a, u64 b) {   // a - b
    return pfma(b, (u64)NEG1_C, a);
}
__device__ __forceinline__ u64 pabs(u64 a) { return a & 0x7FFFFFFF7FFFFFFFULL; }
__device__ __forceinline__ float plo(u64 a) { return __uint_as_float((unsigned)a); }
__device__ __forceinline__ float phi(u64 a) { return __uint_as_float((unsigned)(a >> 32)); }
__device__ __forceinline__ u64 ppack(float lo, float hi) {
    return ((u64)__float_as_uint(hi) << 32) | (u64)__float_as_uint(lo);
}

struct Row { u64 a, b; };   // a = cols (4t,4t+1), b = cols (4t+2,4t+3)

__device__ __forceinline__ Row ldrow(const float* __restrict__ rowbase, int t) {
    ulonglong2 q = *(reinterpret_cast<const ulonglong2*>(rowbase) + t);
    Row r; r.a = q.x; r.b = q.y; return r;
}

// shifted column pairs for one plane's cur row:
// A=(c[-1],c0)  Bp=(c1,c2)  Cp=(c3,c[+4])
__device__ __forceinline__ void shifts(Row c, const float* __restrict__ rowbase,
                                       int tid, int lane, u64& A, u64& Bp, u64& Cp) {
    float c0 = plo(c.a), c1 = phi(c.a), c2 = plo(c.b), c3 = phi(c.b);
    float vL = __shfl_up_sync(0xFFFFFFFFu, c3, 1);
    float vR = __shfl_down_sync(0xFFFFFFFFu, c0, 1);
    if (lane == 0 && tid > 0)       vL = rowbase[4 * tid - 1];
    if (lane == 31 && tid < NT - 1) vR = rowbase[4 * tid + 4];
    A  = ppack(vL, c0);
    Bp = ppack(c1, c2);
    Cp = ppack(c3, vR);
}

// Raw (unscaled) residuals for 2 columns.
// mass_raw = (ur-ul)+(vt-vb)                        -> *0.5  at finalize
// momu_raw = (du2+duv) - 4*IRE*(ur+ul+ut+ub-4um)    -> *0.25 at finalize
__device__ __forceinline__ void resid_slot(
    u64 um, u64 ul, u64 ur, u64 ub, u64 ut,
    u64 vm, u64 vl, u64 vr, u64 vb, u64 vt,
    u64 TWO, u64 NEG4, u64 N4IRE,
    u64& mass, u64& momu, u64& momv)
{
    u64 t1 = psub(ur, ul);
    u64 t3 = psub(vt, vb);
    mass = padd(t1, t3);

    u64 s1 = padd(ur, ul);
    u64 w1 = pfma(um, TWO, s1);
    u64 du2 = pmul(t1, w1);                 // (ur+um)^2-(ul+um)^2  (raw)
    u64 s3 = padd(vt, vb);
    u64 w3 = pfma(vm, TWO, s3);
    u64 dv2 = pmul(t3, w3);

    u64 p1 = padd(ut, um), p2 = padd(vt, vm);
    u64 p3 = padd(ub, um), p4 = padd(vb, vm);
    u64 duv = psub(pmul(p1, p2), pmul(p3, p4));

    u64 p6 = padd(ur, um), p8 = padd(ul, um);
    u64 p5 = padd(vr, vm), p7 = padd(vl, vm);
    u64 dvu = psub(pmul(p5, p6), pmul(p7, p8));

    u64 Xu = padd(du2, duv);
    u64 Xv = padd(dvu, dv2);

    u64 s5 = padd(ut, ub);
    u64 s6 = padd(s1, s5);
    u64 Yu = pfma(um, NEG4, s6);            // ur+ul+ut+ub-4um
    momu = pfma(Yu, N4IRE, Xu);

    u64 s8 = padd(vr, vl);
    u64 s9 = padd(s3, s8);
    u64 Yv = pfma(vm, NEG4, s9);
    momv = pfma(Yv, N4IRE, Xv);
}

__global__ __launch_bounds__(NT) void loss_kernel(const float* __restrict__ pred,
                                                  const float* __restrict__ trut)
{
    const int bx = blockIdx.x;
    const int img = bx >> 5;               // / NSTRIPS
    const int strip = bx & (NSTRIPS - 1);
    const int y0 = strip * RB;
    const int tid = threadIdx.x;
    const int lane = tid & 31;

    const size_t HW = (size_t)H * W;
    const float* __restrict__ pu = pred + (size_t)img * 2 * HW;
    const float* __restrict__ pv = pu + HW;
    const float* __restrict__ tu = trut + (size_t)img * 2 * HW;
    const float* __restrict__ tv = tu + HW;

    const u64 TWO   = pdup(2.0f);
    const u64 NEG4  = pdup(-4.0f);
    const u64 N4IRE = pdup(-(4.0f * (1.0f / 400.0f)));   // -0.01

    Row uPp = {0, 0}, vPp = {0, 0}, uTp = {0, 0}, vTp = {0, 0};
    if (y0 > 0) {
        uPp = ldrow(pu + (size_t)(y0 - 1) * W, tid);
        vPp = ldrow(pv + (size_t)(y0 - 1) * W, tid);
        uTp = ldrow(tu + (size_t)(y0 - 1) * W, tid);
        vTp = ldrow(tv + (size_t)(y0 - 1) * W, tid);
    }
    Row uPc = ldrow(pu + (size_t)y0 * W, tid);
    Row vPc = ldrow(pv + (size_t)y0 * W, tid);
    Row uTc = ldrow(tu + (size_t)y0 * W, tid);
    Row vTc = ldrow(tv + (size_t)y0 * W, tid);
    Row uPn = ldrow(pu + (size_t)(y0 + 1) * W, tid);
    Row vPn = ldrow(pv + (size_t)(y0 + 1) * W, tid);
    Row uTn = ldrow(tu + (size_t)(y0 + 1) * W, tid);
    Row vTn = ldrow(tv + (size_t)(y0 + 1) * W, tid);

    u64 accM0 = 0, accM1 = 0, accO0 = 0, accO1 = 0, accL0 = 0, accL1 = 0;

    #pragma unroll 4
    for (int r = 0; r < RB; ++r) {
        const int y = y0 + r;

        // prefetch row y+2 (consumed as 'next' at iteration r+1)
        Row nuP = {0, 0}, nvP = {0, 0}, nuT = {0, 0}, nvT = {0, 0};
        const int yn = y + 2;
        if (r < RB - 1 && yn < H) {
            nuP = ldrow(pu + (size_t)yn * W, tid);
            nvP = ldrow(pv + (size_t)yn * W, tid);
            nuT = ldrow(tu + (size_t)yn * W, tid);
            nvT = ldrow(tv + (size_t)yn * W, tid);
        }

        // L1 (all points)
        accL0 = padd(accL0, pabs(psub(uPc.a, uTc.a)));
        accL1 = padd(accL1, pabs(psub(uPc.b, uTc.b)));
        accL0 = padd(accL0, pabs(psub(vPc.a, vTc.a)));
        accL1 = padd(accL1, pabs(psub(vPc.b, vTc.b)));

        if (y >= 1 && y <= H - 2) {
            u64 uA, uB, uC, vA, vB, vC;
            // pred
            shifts(uPc, pu + (size_t)y * W, tid, lane, uA, uB, uC);
            shifts(vPc, pv + (size_t)y * W, tid, lane, vA, vB, vC);
            u64 mP0, oP0, wP0, mP1, oP1, wP1;
            resid_slot(uPc.a, uPp.a, uPn.a, uA, uB,
                       vPc.a, vPp.a, vPn.a, vA, vB,
                       TWO, NEG4, N4IRE, mP0, oP0, wP0);
            resid_slot(uPc.b, uPp.b, uPn.b, uB, uC,
                       vPc.b, vPp.b, vPn.b, vB, vC,
                       TWO, NEG4, N4IRE, mP1, oP1, wP1);
            // trut
            shifts(uTc, tu + (size_t)y * W, tid, lane, uA, uB, uC);
            shifts(vTc, tv + (size_t)y * W, tid, lane, vA, vB, vC);
            u64 mT0, oT0, wT0, mT1, oT1, wT1;
            resid_slot(uTc.a, uTp.a, uTn.a, uA, uB,
                       vTc.a, vTp.a, vTn.a, vA, vB,
                       TWO, NEG4, N4IRE, mT0, oT0, wT0);
            resid_slot(uTc.b, uTp.b, uTn.b, uB, uC,
                       vTc.b, vTp.b, vTn.b, vB, vC,
                       TWO, NEG4, N4IRE, mT1, oT1, wT1);

            accM0 = padd(accM0, pabs(psub(mT0, mP0)));
            accM1 = padd(accM1, pabs(psub(mT1, mP1)));
            accO0 = padd(accO0, padd(pabs(psub(oT0, oP0)), pabs(psub(wT0, wP0))));
            accO1 = padd(accO1, padd(pabs(psub(oT1, oP1)), pabs(psub(wT1, wP1))));
        }

        // rotate sliding window
        uPp = uPc; uPc = uPn; uPn = nuP;
        vPp = vPc; vPc = vPn; vPn = nvP;
        uTp = uTc; uTc = uTn; uTn = nuT;
        vTp = vTc; vTc = vTn; vTn = nvT;
    }

    // mask out boundary columns 0 and 511 (excluded from stencil sums)
    if (tid == 0)      { accM0 &= 0xFFFFFFFF00000000ULL; accO0 &= 0xFFFFFFFF00000000ULL; }
    if (tid == NT - 1) { accM1 &= 0x00000000FFFFFFFFULL; accO1 &= 0x00000000FFFFFFFFULL; }

    float sM = plo(accM0) + phi(accM0) + plo(accM1) + phi(accM1);
    float sO = plo(accO0) + phi(accO0) + plo(accO1) + phi(accO1);
    float sL = plo(accL0) + phi(accL0) + plo(accL1) + phi(accL1);

    // block reduce (4 warps)
    const unsigned FULL = 0xFFFFFFFFu;
    #pragma unroll
    for (int off = 16; off > 0; off >>= 1) {
        sM += __shfl_down_sync(FULL, sM, off);
        sO += __shfl_down_sync(FULL, sO, off);
        sL += __shfl_down_sync(FULL, sL, off);
    }
    __shared__ float sh[4][3];
    const int wid = tid >> 5;
    if (lane == 0) { sh[wid][0] = sM; sh[wid][1] = sO; sh[wid][2] = sL; }
    __syncthreads();
    if (tid == 0) {
        float m = sh[0][0] + sh[1][0] + sh[2][0] + sh[3][0];
        float o = sh[0][1] + sh[1][1] + sh[2][1] + sh[3][1];
        float l = sh[0][2] + sh[1][2] + sh[2][2] + sh[3][2];
        atomicAdd(&g_sums[0], (double)m);
        atomicAdd(&g_sums[1], (double)o);
        atomicAdd(&g_sums[2], (double)l);
    }
}

__global__ void finalize_kernel(float* __restrict__ out) {
    const double NM = (double)B * (H - 2) * (W - 2);   // 64*510*510
    const double NL = (double)B * 2.0 * H * W;         // 64*2*512*512
    double m = g_sums[0];
    double o = g_sums[1];
    double l = g_sums[2];
    double lossMass = 0.5  * m / NM;
    double lossMom  = 0.25 * o / NM;
    double lossL1   = l / NL;
    out[0] = (float)((lossMass * 5.0 + lossMom * 25.0 + lossL1) / 3.0);
    // Reset for the next graph replay (re-establishes the entry invariant).
    g_sums[0] = 0.0;
    g_sums[1] = 0.0;
    g_sums[2] = 0.0;
}

extern "C" void kernel_launch(void* const* d_in, const int* in_sizes, int n_in,
                              void* d_out, int out_size) {
    const float* pred = (const float*)d_in[0];
    const float* trut = (const float*)d_in[1];
    float* out = (float*)d_out;

    loss_kernel<<<B * NSTRIPS, NT>>>(pred, trut);
    finalize_kernel<<<1, 1>>>(out);
}